// round 5
// baseline (speedup 1.0000x reference)
#include <cuda_runtime.h>
#include <cuda_bf16.h>
#include <cstdint>

// out[b,s,e] = W_emb[e, tokens[b,s]] + W_pos[s,e]
// tokens: int32 (B,S)=(8,2048), W_emb: fp32 (E,V)=(512,50257),
// W_pos: fp32 (S,E)=(2048,512), out: fp32 (B,S,E)
//
// R4 strategy: counting-sort the 16384 tokens (zero/hist/scan/scatter prelude,
// ~µs each), then gather TRANSPOSED: warp lanes hold 32 consecutive *sorted*
// tokens reading the same e-row -> lanes span ~400B of the row, so each gather
// LDG touches ~4-5 cache lines instead of 32. This cuts L1tex wavefronts ~7x
// and dedups L2 sector requests to near the distinct-sector minimum (~95 MB).
// Results staged in an smem tile (stride-133 rows, conflict-free both phases),
// written back coalesced with the W_pos add fused.

static constexpr int B = 8, S = 2048, E = 512, V = 50257;
static constexpr int BS = B * S;            // 16384
static constexpr int TPB_TOK = 64;          // tokens per tile
static constexpr int ECH = 128;             // e per chunk
static constexpr int NCH = E / ECH;         // 4 phases (blockIdx.y slowest)
static constexpr int ROWP = ECH + 5;        // 133: gcd(133%32=5,32)=1 -> conflict-free

// scratch (allocation-free rule: __device__ globals)
__device__ unsigned int g_hist[V];
__device__ unsigned int g_sorted[BS];       // (tok << 14) | bs

// ---------------- prelude: counting sort ----------------

__global__ void zero_kernel() {
    int i = blockIdx.x * blockDim.x + threadIdx.x;
    if (i < V) g_hist[i] = 0u;
}

__global__ void hist_kernel(const int* __restrict__ tokens) {
    int i = blockIdx.x * blockDim.x + threadIdx.x;
    if (i < BS) atomicAdd(&g_hist[tokens[i]], 1u);
}

__global__ __launch_bounds__(1024) void scan_kernel() {
    __shared__ unsigned int ssum[1024];
    const int C = (V + 1023) / 1024;        // 50 bins per thread
    int tid = threadIdx.x;
    int base = tid * C;

    unsigned int sum = 0;
    for (int i = 0; i < C; i++) {
        int idx = base + i;
        if (idx < V) sum += g_hist[idx];
    }
    ssum[tid] = sum;
    __syncthreads();
    // Hillis-Steele inclusive scan over 1024 partials
    for (int off = 1; off < 1024; off <<= 1) {
        unsigned int v = (tid >= off) ? ssum[tid - off] : 0u;
        __syncthreads();
        ssum[tid] += v;
        __syncthreads();
    }
    unsigned int run = (tid > 0) ? ssum[tid - 1] : 0u;  // exclusive prefix
    for (int i = 0; i < C; i++) {
        int idx = base + i;
        if (idx < V) {
            unsigned int c = g_hist[idx];
            g_hist[idx] = run;              // bin start offset
            run += c;
        }
    }
}

__global__ void scatter_kernel(const int* __restrict__ tokens) {
    int i = blockIdx.x * blockDim.x + threadIdx.x;
    if (i < BS) {
        int t = tokens[i];
        unsigned int p = atomicAdd(&g_hist[t], 1u);
        // order within equal-token runs is nondeterministic, but each entry
        // writes only its own output rows -> final output is deterministic
        g_sorted[p] = ((unsigned int)t << 14) | (unsigned int)i;
    }
}

// ---------------- main: sorted transposed gather ----------------

__global__ __launch_bounds__(256) void gather_sorted_kernel(
    const float* __restrict__ W_emb,
    const float* __restrict__ W_pos,
    float* __restrict__ out)
{
    __shared__ float tile[TPB_TOK * ROWP];
    __shared__ int s_tok[TPB_TOK];
    __shared__ int s_bs[TPB_TOK];

    int tid = threadIdx.x;
    int tok_base = blockIdx.x * TPB_TOK;
    int e0 = blockIdx.y * ECH;              // e-chunk slowest in launch order

    if (tid < TPB_TOK) {
        unsigned int v = g_sorted[tok_base + tid];
        s_tok[tid] = (int)(v >> 14);
        s_bs[tid]  = (int)(v & 16383u);
    }
    __syncthreads();

    int lane = tid & 31;
    int w    = tid >> 5;                    // warp id 0..7

    // Gather phase: warp lanes = 32 consecutive sorted tokens, same e-row
    // per LDG -> ~4-5 lines per access. Warp w covers e_local {w, w+8, ...}.
    #pragma unroll
    for (int g = 0; g < 2; g++) {
        int row = g * 32 + lane;
        int tok = s_tok[row];
        const float* base = W_emb + (size_t)e0 * V + tok;
        #pragma unroll
        for (int i = 0; i < 16; i++) {
            int e_local = w + i * 8;
            // stride-133 rows: lanes vary row -> bank (5*lane)%32, conflict-free
            tile[row * ROWP + e_local] = __ldg(base + (size_t)e_local * V);
        }
    }
    __syncthreads();

    // Store phase: warp lanes span 32 consecutive e -> conflict-free LDS,
    // coalesced W_pos load (L2-resident) and coalesced output store.
    int e_local = tid & 127;
    int tsub    = tid >> 7;                 // 0..1
    #pragma unroll
    for (int p = 0; p < 32; p++) {
        int row = p * 2 + tsub;
        int bs  = s_bs[row];
        int s   = bs & (S - 1);
        float val = tile[row * ROWP + e_local]
                  + __ldg(W_pos + (size_t)s * E + e0 + e_local);
        // streaming store: keep write-once output from evicting gather sectors
        __stcs(out + (size_t)bs * E + e0 + e_local, val);
    }
}

// ---------------- launch ----------------

extern "C" void kernel_launch(void* const* d_in, const int* in_sizes, int n_in,
                              void* d_out, int out_size)
{
    const int*   tokens = (const int*)d_in[0];
    const float* W_emb  = (const float*)d_in[1];
    const float* W_pos  = (const float*)d_in[2];
    float*       out    = (float*)d_out;

    zero_kernel<<<(V + 1023) / 1024, 1024>>>();
    hist_kernel<<<BS / 256, 256>>>(tokens);
    scan_kernel<<<1, 1024>>>();
    scatter_kernel<<<BS / 256, 256>>>(tokens);

    dim3 grid(BS / TPB_TOK, NCH);           // (256, 4), e-chunk slowest
    gather_sorted_kernel<<<grid, 256>>>(W_emb, W_pos, out);
}

// round 6
// speedup vs baseline: 2.1305x; 2.1305x over previous
#include <cuda_runtime.h>
#include <cuda_bf16.h>
#include <cstdint>

// out[b,s,e] = W_emb[e, tokens[b,s]] + W_pos[s,e]
// tokens: int32 (B,S)=(8,2048), W_emb: fp32 (E,V)=(512,50257),
// W_pos: fp32 (S,E)=(2048,512), out: fp32 (B,S,E)
//
// R5: COARSE bucket sort (16-slot bins, NBINS=3142) replaces the full
// counting sort — identical warp-level locality (32 grouped tokens span
// ~98 slots = ~4 cache lines per gather warp-LDG vs 32 unsorted) at a
// fraction of the prelude cost (scan shrinks 50257 -> 3142 bins).
// Main kernel: 32 tokens/block, e-chunks looped inside, 17KB tile ->
// ~8 blocks/SM, conflict-free smem both phases, coalesced stores + W_pos.

static constexpr int B = 8, S = 2048, E = 512, V = 50257;
static constexpr int BS = B * S;                 // 16384
static constexpr int NBINS = (V + 15) >> 4;      // 3142 bins of 16 vocab slots
static constexpr int TPB_TOK = 32;               // tokens per block
static constexpr int ECH = 128;                  // e per chunk
static constexpr int NCH = E / ECH;              // 4 chunks, looped in-block
static constexpr int ROWP = ECH + 5;             // 133: (5*lane)%32 conflict-free

// scratch (allocation-free rule: __device__ globals)
__device__ unsigned int g_hist[NBINS];
__device__ unsigned int g_sorted[BS];            // (tok << 14) | bs

// ---------------- prelude: coarse bucket sort ----------------

__global__ void zero_kernel() {
    int i = blockIdx.x * blockDim.x + threadIdx.x;
    if (i < NBINS) g_hist[i] = 0u;
}

__global__ void hist_kernel(const int* __restrict__ tokens) {
    int i = blockIdx.x * blockDim.x + threadIdx.x;
    if (i < BS) atomicAdd(&g_hist[tokens[i] >> 4], 1u);
}

__global__ __launch_bounds__(1024) void scan_kernel() {
    __shared__ unsigned int ssum[1024];
    const int C = (NBINS + 1023) / 1024;         // 4 bins per thread
    int tid = threadIdx.x;
    int base = tid * C;

    unsigned int sum = 0;
    #pragma unroll
    for (int i = 0; i < C; i++) {
        int idx = base + i;
        if (idx < NBINS) sum += g_hist[idx];
    }
    ssum[tid] = sum;
    __syncthreads();
    // Hillis-Steele inclusive scan over 1024 partials
    for (int off = 1; off < 1024; off <<= 1) {
        unsigned int v = (tid >= off) ? ssum[tid - off] : 0u;
        __syncthreads();
        ssum[tid] += v;
        __syncthreads();
    }
    unsigned int run = (tid > 0) ? ssum[tid - 1] : 0u;   // exclusive prefix
    #pragma unroll
    for (int i = 0; i < C; i++) {
        int idx = base + i;
        if (idx < NBINS) {
            unsigned int c = g_hist[idx];
            g_hist[idx] = run;                   // bin start offset
            run += c;
        }
    }
}

__global__ void scatter_kernel(const int* __restrict__ tokens) {
    int i = blockIdx.x * blockDim.x + threadIdx.x;
    if (i < BS) {
        int t = tokens[i];
        unsigned int p = atomicAdd(&g_hist[t >> 4], 1u);
        // order within a bin is nondeterministic, but each entry writes only
        // its own output rows -> final output is deterministic
        g_sorted[p] = ((unsigned int)t << 14) | (unsigned int)i;
    }
}

// ---------------- main: bucketed transposed gather ----------------

__global__ __launch_bounds__(256)
void gather_main_kernel(const float* __restrict__ W_emb,
                        const float* __restrict__ W_pos,
                        float* __restrict__ out)
{
    __shared__ float tile[TPB_TOK * ROWP];       // 17,024 B
    __shared__ unsigned int s_ent[TPB_TOK];

    int tid  = threadIdx.x;
    int lane = tid & 31;
    int w    = tid >> 5;                         // warp id 0..7

    if (tid < TPB_TOK) s_ent[tid] = g_sorted[blockIdx.x * TPB_TOK + tid];
    __syncthreads();

    // this lane's gather token — 32 bucketed tokens span ~98 vocab slots,
    // so each gather warp-LDG touches ~4 cache lines (vs 32 unsorted)
    int tok = (int)(s_ent[lane] >> 14);
    const float* colbase = W_emb + tok;

    int e_lo = tid & 127;                        // store-phase e within chunk
    int tsub = tid >> 7;                         // 0..1

    #pragma unroll
    for (int c = 0; c < NCH; c++) {
        int e0 = c * ECH;

        // gather: warp w covers e-rows [w*16, w*16+16); lanes = 32 tokens
        #pragma unroll
        for (int i = 0; i < 16; i++) {
            int el = w * 16 + i;
            // STS stride ROWP=133 across lanes -> banks (5*lane)%32, clean
            tile[lane * ROWP + el] = __ldg(colbase + (size_t)(e0 + el) * V);
        }
        __syncthreads();

        // store: warp lanes span 32 consecutive e -> conflict-free LDS,
        // coalesced W_pos load (L2-resident) and coalesced output store
        #pragma unroll
        for (int p = 0; p < 16; p++) {
            int row = p * 2 + tsub;
            unsigned int ent = s_ent[row];       // broadcast LDS
            int bs = (int)(ent & 16383u);
            int s  = bs & (S - 1);
            float v = tile[row * ROWP + e_lo]
                    + __ldg(W_pos + (size_t)s * E + e0 + e_lo);
            // streaming store: write-once output must not evict gather sectors
            __stcs(out + (size_t)bs * E + e0 + e_lo, v);
        }
        __syncthreads();                          // before tile is overwritten
    }
}

// ---------------- launch ----------------

extern "C" void kernel_launch(void* const* d_in, const int* in_sizes, int n_in,
                              void* d_out, int out_size)
{
    const int*   tokens = (const int*)d_in[0];
    const float* W_emb  = (const float*)d_in[1];
    const float* W_pos  = (const float*)d_in[2];
    float*       out    = (float*)d_out;

    zero_kernel<<<(NBINS + 255) / 256, 256>>>();
    hist_kernel<<<BS / 256, 256>>>(tokens);
    scan_kernel<<<1, 1024>>>();
    scatter_kernel<<<BS / 256, 256>>>(tokens);

    gather_main_kernel<<<BS / TPB_TOK, 256>>>(W_emb, W_pos, out);  // 512 blocks
}

// round 7
// speedup vs baseline: 2.3787x; 1.1165x over previous
#include <cuda_runtime.h>
#include <cuda_bf16.h>
#include <cstdint>

// out[b,s,e] = W_emb[e, tokens[b,s]] + W_pos[s,e]
// tokens: int32 (B,S)=(8,2048), W_emb: fp32 (E,V)=(512,50257),
// W_pos: fp32 (S,E)=(2048,512), out: fp32 (B,S,E)
//
// R6 vs R5:
//  - main kernel: e-chunk moved from an in-block loop to blockIdx.y ->
//    grid (512,4) = 2048 small independent blocks. ~8 resident blocks/SM
//    overlap the gather->store sync latency; wave tail shrinks 4x.
//  - prelude: zero_kernel replaced by cudaMemsetAsync node; hist/scatter
//    use 128x128 grids for better atomic latency hiding.

static constexpr int B = 8, S = 2048, E = 512, V = 50257;
static constexpr int BS = B * S;                 // 16384
static constexpr int NBINS = (V + 15) >> 4;      // 3142 bins of 16 vocab slots
static constexpr int TPB_TOK = 32;               // tokens per block
static constexpr int ECH = 128;                  // e per chunk
static constexpr int NCH = E / ECH;              // 4 chunks (blockIdx.y)
static constexpr int ROWP = ECH + 5;             // 133: (5*lane)%32 conflict-free

// scratch (allocation-free rule: __device__ globals)
__device__ unsigned int g_hist[NBINS];
__device__ unsigned int g_sorted[BS];            // (tok << 14) | bs

// ---------------- prelude: coarse bucket sort ----------------

__global__ void hist_kernel(const int* __restrict__ tokens) {
    int i = blockIdx.x * blockDim.x + threadIdx.x;
    if (i < BS) atomicAdd(&g_hist[tokens[i] >> 4], 1u);
}

__global__ __launch_bounds__(1024) void scan_kernel() {
    __shared__ unsigned int ssum[1024];
    const int C = (NBINS + 1023) / 1024;         // 4 bins per thread
    int tid = threadIdx.x;
    int base = tid * C;

    unsigned int sum = 0;
    #pragma unroll
    for (int i = 0; i < C; i++) {
        int idx = base + i;
        if (idx < NBINS) sum += g_hist[idx];
    }
    ssum[tid] = sum;
    __syncthreads();
    for (int off = 1; off < 1024; off <<= 1) {   // Hillis-Steele inclusive
        unsigned int v = (tid >= off) ? ssum[tid - off] : 0u;
        __syncthreads();
        ssum[tid] += v;
        __syncthreads();
    }
    unsigned int run = (tid > 0) ? ssum[tid - 1] : 0u;   // exclusive prefix
    #pragma unroll
    for (int i = 0; i < C; i++) {
        int idx = base + i;
        if (idx < NBINS) {
            unsigned int c = g_hist[idx];
            g_hist[idx] = run;                   // bin start offset
            run += c;
        }
    }
}

__global__ void scatter_kernel(const int* __restrict__ tokens) {
    int i = blockIdx.x * blockDim.x + threadIdx.x;
    if (i < BS) {
        int t = tokens[i];
        unsigned int p = atomicAdd(&g_hist[t >> 4], 1u);
        // order within a bin is nondeterministic, but each entry writes only
        // its own output rows -> final output is deterministic
        g_sorted[p] = ((unsigned int)t << 14) | (unsigned int)i;
    }
}

// ---------------- main: bucketed transposed gather ----------------

__global__ __launch_bounds__(256)
void gather_main_kernel(const float* __restrict__ W_emb,
                        const float* __restrict__ W_pos,
                        float* __restrict__ out)
{
    __shared__ float tile[TPB_TOK * ROWP];       // 17,024 B
    __shared__ unsigned int s_ent[TPB_TOK];

    int tid  = threadIdx.x;
    int lane = tid & 31;
    int w    = tid >> 5;                         // warp id 0..7
    int e0   = blockIdx.y * ECH;                 // e-chunk slowest in launch order

    if (tid < TPB_TOK) s_ent[tid] = g_sorted[blockIdx.x * TPB_TOK + tid];
    __syncthreads();

    // gather: lanes = 32 bucketed tokens (span ~98 vocab slots -> ~4 lines
    // per warp-LDG). Warp w covers e_local [w*16, w*16+16). MLP=16.
    {
        int tok = (int)(s_ent[lane] >> 14);
        const float* colbase = W_emb + (size_t)e0 * V + tok;
        #pragma unroll
        for (int i = 0; i < 16; i++) {
            int el = w * 16 + i;
            // STS banks (5*lane + el)%32 -> all distinct, conflict-free
            tile[lane * ROWP + el] = __ldg(colbase + (size_t)el * V);
        }
    }
    __syncthreads();

    // store: warp lanes span 32 consecutive e -> conflict-free LDS,
    // coalesced W_pos load (L2-resident) and coalesced output store.
    {
        int e_lo = tid & 127;
        int tsub = tid >> 7;                     // 0..1
        #pragma unroll
        for (int p = 0; p < 16; p++) {
            int row = p * 2 + tsub;
            unsigned int ent = s_ent[row];       // broadcast LDS
            int bs = (int)(ent & 16383u);
            int s  = bs & (S - 1);
            float v = tile[row * ROWP + e_lo]
                    + __ldg(W_pos + (size_t)s * E + e0 + e_lo);
            // streaming store: write-once output must not evict gather sectors
            __stcs(out + (size_t)bs * E + e0 + e_lo, v);
        }
    }
}

// ---------------- launch ----------------

extern "C" void kernel_launch(void* const* d_in, const int* in_sizes, int n_in,
                              void* d_out, int out_size)
{
    const int*   tokens = (const int*)d_in[0];
    const float* W_emb  = (const float*)d_in[1];
    const float* W_pos  = (const float*)d_in[2];
    float*       out    = (float*)d_out;

    // zero the bin histogram via a memset node (replaces zero_kernel launch)
    void* hist_ptr = nullptr;
    cudaGetSymbolAddress(&hist_ptr, g_hist);
    cudaMemsetAsync(hist_ptr, 0, NBINS * sizeof(unsigned int));

    hist_kernel<<<BS / 128, 128>>>(tokens);      // 128 blocks x 128
    scan_kernel<<<1, 1024>>>();
    scatter_kernel<<<BS / 128, 128>>>(tokens);   // 128 blocks x 128

    dim3 grid(BS / TPB_TOK, NCH);                // (512, 4)
    gather_main_kernel<<<grid, 256>>>(W_emb, W_pos, out);
}